// round 1
// baseline (speedup 1.0000x reference)
#include <cuda_runtime.h>
#include <math.h>

#define T_TOK 16384
#define DDIM  512
#define HDIM  2048
#define NEXP  16
#define TOPK  4

#define MT   32     // tokens per FFN tile
#define NC   64     // H-chunk width
#define KT1  32     // GEMM1 k-tile
#define KT2  8      // GEMM2 k-subtile

// routing scratch (static device globals: allocation-free)
__device__ int   g_count[NEXP];
__device__ int   g_tok [NEXP * T_TOK];
__device__ float g_gate[NEXP * T_TOK];

// ---------------------------------------------------------------------------
// K0: zero output + counts
// ---------------------------------------------------------------------------
__global__ void zero_kernel(float4* __restrict__ out, int n4) {
    int i = blockIdx.x * blockDim.x + threadIdx.x;
    if (i < n4) out[i] = make_float4(0.f, 0.f, 0.f, 0.f);
    if (blockIdx.x == 0 && threadIdx.x < NEXP) g_count[threadIdx.x] = 0;
}

// ---------------------------------------------------------------------------
// K1: router — logits, top-4, softmax, append to expert lists
// one warp handles 4 tokens; block = 256 threads = 8 warps = 32 tokens
// ---------------------------------------------------------------------------
__global__ __launch_bounds__(256)
void router_kernel(const float* __restrict__ x,
                   const float* __restrict__ rw,
                   const float* __restrict__ rb) {
    __shared__ float s_rw[DDIM * NEXP];   // 32 KB
    __shared__ float s_rb[NEXP];

    for (int i = threadIdx.x; i < DDIM * NEXP; i += 256) s_rw[i] = rw[i];
    if (threadIdx.x < NEXP) s_rb[threadIdx.x] = rb[threadIdx.x];
    __syncthreads();

    int warp = threadIdx.x >> 5;
    int lane = threadIdx.x & 31;
    int t0 = (blockIdx.x * 8 + warp) * 4;
    if (t0 >= T_TOK) return;

    float acc[4][NEXP];
#pragma unroll
    for (int tt = 0; tt < 4; tt++)
#pragma unroll
        for (int e = 0; e < NEXP; e++) acc[tt][e] = 0.f;

#pragma unroll 4
    for (int di = 0; di < 16; di++) {
        int d = di * 32 + lane;
        float xv[4];
#pragma unroll
        for (int tt = 0; tt < 4; tt++)
            xv[tt] = x[(size_t)(t0 + tt) * DDIM + d];
#pragma unroll
        for (int e = 0; e < NEXP; e++) {
            float w = s_rw[d * NEXP + e];
#pragma unroll
            for (int tt = 0; tt < 4; tt++) acc[tt][e] = fmaf(xv[tt], w, acc[tt][e]);
        }
    }

    // cross-lane reduction: every lane ends with full sums
#pragma unroll
    for (int tt = 0; tt < 4; tt++)
#pragma unroll
        for (int e = 0; e < NEXP; e++) {
            float v = acc[tt][e];
#pragma unroll
            for (int off = 16; off > 0; off >>= 1)
                v += __shfl_xor_sync(0xffffffffu, v, off);
            acc[tt][e] = v;
        }

    if (lane == 0) {
#pragma unroll
        for (int tt = 0; tt < 4; tt++) {
            int t = t0 + tt;
            float v[NEXP];
#pragma unroll
            for (int e = 0; e < NEXP; e++) v[e] = acc[tt][e] + s_rb[e];

            float sv[TOPK]; int si[TOPK];
#pragma unroll
            for (int k = 0; k < TOPK; k++) {
                float bm = -1e30f; int bi = 0;
#pragma unroll
                for (int e = 0; e < NEXP; e++)
                    if (v[e] > bm) { bm = v[e]; bi = e; }
                sv[k] = bm; si[k] = bi; v[bi] = -1e30f;
            }
            float mx = sv[0];
            float s = 0.f, g[TOPK];
#pragma unroll
            for (int k = 0; k < TOPK; k++) { g[k] = __expf(sv[k] - mx); s += g[k]; }
            float inv = 1.f / s;
#pragma unroll
            for (int k = 0; k < TOPK; k++) {
                int e = si[k];
                int pos = atomicAdd(&g_count[e], 1);
                g_tok [e * T_TOK + pos] = t;
                g_gate[e * T_TOK + pos] = g[k] * inv;
            }
        }
    }
}

// ---------------------------------------------------------------------------
// K2: fused grouped FFN.  block = 256 threads, tile = 32 tokens of one expert.
// smem: Xs[32][512] | W1s[32][64] | Hs[32][64] | W2s[8][512]  (96 KB dynamic)
// ---------------------------------------------------------------------------
__global__ __launch_bounds__(256, 1)
void ffn_kernel(const float* __restrict__ x,
                const float* __restrict__ w1, const float* __restrict__ b1,
                const float* __restrict__ w2, const float* __restrict__ b2,
                float* __restrict__ out) {
    int e  = blockIdx.y;
    int cnt = g_count[e];
    int m0 = blockIdx.x * MT;
    if (m0 >= cnt) return;
    int nrows = min(MT, cnt - m0);

    extern __shared__ float smem[];
    float* Xs  = smem;                  // MT*DDIM
    float* W1s = Xs  + MT * DDIM;       // KT1*NC
    float* Hs  = W1s + KT1 * NC;        // MT*NC
    float* W2s = Hs  + MT * NC;         // KT2*DDIM
    __shared__ int   s_tok[MT];
    __shared__ float s_gate[MT];

    int tid = threadIdx.x;
    if (tid < MT) {
        if (tid < nrows) {
            s_tok [tid] = g_tok [e * T_TOK + m0 + tid];
            s_gate[tid] = g_gate[e * T_TOK + m0 + tid];
        } else { s_tok[tid] = -1; s_gate[tid] = 0.f; }
    }
    __syncthreads();

    // stage X tile
    for (int i = tid; i < MT * DDIM / 4; i += 256) {
        int m = i / (DDIM / 4);
        int q = i % (DDIM / 4);
        float4 v = make_float4(0.f, 0.f, 0.f, 0.f);
        int tok = s_tok[m];
        if (tok >= 0) v = ((const float4*)(x + (size_t)tok * DDIM))[q];
        ((float4*)Xs)[i] = v;
    }

    const float* w1e = w1 + (size_t)e * DDIM * HDIM;
    const float* w2e = w2 + (size_t)e * HDIM * DDIM;

    // GEMM2 register accumulator Y[32][512]: thread owns 4m x 16n
    int tn2 = tid & 31;        // n = tn2*16 + j
    int tm2 = tid >> 5;        // m = tm2*4 + i
    int tn1 = tid & 15;        // gemm1: n = nc + tn1*4 + j
    int tm1 = tid >> 4;        // gemm1: m = tm1*2 + i

    float Y[4][16];
#pragma unroll
    for (int i = 0; i < 4; i++)
#pragma unroll
        for (int j = 0; j < 16; j++) Y[i][j] = 0.f;

    for (int nc = 0; nc < HDIM; nc += NC) {
        // ---- GEMM1: H[32][64] = X[32][512] @ W1[:, nc:nc+64] ----
        float acc1[2][4];
#pragma unroll
        for (int i = 0; i < 2; i++)
#pragma unroll
            for (int j = 0; j < 4; j++) acc1[i][j] = 0.f;

        for (int kt = 0; kt < DDIM; kt += KT1) {
            __syncthreads();
            for (int i = tid; i < KT1 * NC / 4; i += 256) {
                int r  = i / (NC / 4);
                int c4 = i % (NC / 4);
                ((float4*)W1s)[i] =
                    *(const float4*)(w1e + (size_t)(kt + r) * HDIM + nc + c4 * 4);
            }
            __syncthreads();
#pragma unroll
            for (int k = 0; k < KT1; k += 4) {
                float4 a0q = *(const float4*)&Xs[(tm1 * 2 + 0) * DDIM + kt + k];
                float4 a1q = *(const float4*)&Xs[(tm1 * 2 + 1) * DDIM + kt + k];
                float a0[4] = {a0q.x, a0q.y, a0q.z, a0q.w};
                float a1[4] = {a1q.x, a1q.y, a1q.z, a1q.w};
#pragma unroll
                for (int kk = 0; kk < 4; kk++) {
                    float4 bq = *(const float4*)&W1s[(k + kk) * NC + tn1 * 4];
                    float bb[4] = {bq.x, bq.y, bq.z, bq.w};
#pragma unroll
                    for (int j = 0; j < 4; j++) {
                        acc1[0][j] = fmaf(a0[kk], bb[j], acc1[0][j]);
                        acc1[1][j] = fmaf(a1[kk], bb[j], acc1[1][j]);
                    }
                }
            }
        }
        __syncthreads();
        // bias + relu -> Hs
#pragma unroll
        for (int i = 0; i < 2; i++)
#pragma unroll
            for (int j = 0; j < 4; j++) {
                float v = acc1[i][j] + b1[e * HDIM + nc + tn1 * 4 + j];
                Hs[(tm1 * 2 + i) * NC + tn1 * 4 + j] = fmaxf(v, 0.f);
            }

        // ---- GEMM2: Y[32][512] += H[32][64] @ W2[nc:nc+64, :] ----
        for (int kt = 0; kt < NC; kt += KT2) {
            __syncthreads();
            for (int i = tid; i < KT2 * DDIM / 4; i += 256) {
                int r  = i / (DDIM / 4);
                int c4 = i % (DDIM / 4);
                ((float4*)W2s)[i] =
                    *(const float4*)(w2e + (size_t)(nc + kt + r) * DDIM + c4 * 4);
            }
            __syncthreads();
#pragma unroll
            for (int k = 0; k < KT2; k++) {
                float a[4];
#pragma unroll
                for (int i = 0; i < 4; i++)
                    a[i] = Hs[(tm2 * 4 + i) * NC + kt + k];
#pragma unroll
                for (int j4 = 0; j4 < 4; j4++) {
                    float4 bq = *(const float4*)&W2s[k * DDIM + tn2 * 16 + j4 * 4];
                    float bb[4] = {bq.x, bq.y, bq.z, bq.w};
#pragma unroll
                    for (int i = 0; i < 4; i++)
#pragma unroll
                        for (int jj = 0; jj < 4; jj++)
                            Y[i][j4 * 4 + jj] = fmaf(a[i], bb[jj], Y[i][j4 * 4 + jj]);
                }
            }
        }
    }

    // epilogue: +b2, *gate, scatter
#pragma unroll
    for (int i = 0; i < 4; i++) {
        int m = tm2 * 4 + i;
        int tok = s_tok[m];
        if (tok < 0) continue;
        float g = s_gate[m];
        float* orow = out + (size_t)tok * DDIM;
#pragma unroll
        for (int j = 0; j < 16; j++) {
            int n = tn2 * 16 + j;
            float v = Y[i][j] + b2[e * DDIM + n];
            atomicAdd(&orow[n], g * v);
        }
    }
}

// ---------------------------------------------------------------------------
extern "C" void kernel_launch(void* const* d_in, const int* in_sizes, int n_in,
                              void* d_out, int out_size) {
    const float* x   = (const float*)d_in[0];
    const float* rw  = (const float*)d_in[1];
    const float* rb  = (const float*)d_in[2];
    const float* w1  = (const float*)d_in[3];
    const float* b1  = (const float*)d_in[4];
    const float* w2  = (const float*)d_in[5];
    const float* b2  = (const float*)d_in[6];
    float* out = (float*)d_out;

    const int smem_bytes = (MT * DDIM + KT1 * NC + MT * NC + KT2 * DDIM) * 4;  // 96 KB
    cudaFuncSetAttribute(ffn_kernel, cudaFuncAttributeMaxDynamicSharedMemorySize,
                         smem_bytes);

    int n4 = T_TOK * DDIM / 4;
    zero_kernel<<<(n4 + 255) / 256, 256>>>((float4*)out, n4);
    router_kernel<<<T_TOK / 32, 256>>>(x, rw, rb);
    dim3 grid(T_TOK / MT, NEXP);
    ffn_kernel<<<grid, 256, smem_bytes>>>(x, w1, b1, w2, b2, out);
}

// round 5
// speedup vs baseline: 21.9192x; 21.9192x over previous
#include <cuda_runtime.h>
#include <cuda_fp16.h>
#include <mma.h>
#include <math.h>
#include <stdint.h>

using namespace nvcuda;

#define T_TOK 16384
#define DDIM  512
#define HDIM  2048
#define NEXP  16
#define TOPK  4

#define MTILE 128
#define BN    128
#define BK    64
#define SA    72            // smem row stride (halves), mult of 8, 144B rows
#define CLD   132           // epilogue float stage stride
#define SLOTS (T_TOK * TOPK + MTILE)

#define DSM_BYTES (MTILE * CLD * 4)   // 67584 > 2*128*72*2 = 36864

// ---------------------------------------------------------------------------
// device scratch (allocation-free)
// ---------------------------------------------------------------------------
__device__ int    g_count[NEXP];
__device__ int    g_off[NEXP];
__device__ int    g_tok [NEXP * T_TOK];
__device__ float  g_gate[NEXP * T_TOK];
__device__ __half d_xh  [(size_t)T_TOK * DDIM];
__device__ __half d_w1t [(size_t)NEXP * HDIM * DDIM];   // [e][n(H)][k(D)]
__device__ __half d_w2t [(size_t)NEXP * DDIM * HDIM];   // [e][n(D)][k(H)]
__device__ __half d_hbuf[(size_t)SLOTS * HDIM];         // fp16 hidden acts

// ---------------------------------------------------------------------------
// K0: zero out + counts
// ---------------------------------------------------------------------------
__global__ void zero_kernel(float4* __restrict__ out, int n4) {
    int i = blockIdx.x * blockDim.x + threadIdx.x;
    if (i < n4) out[i] = make_float4(0.f, 0.f, 0.f, 0.f);
    if (blockIdx.x == 0 && threadIdx.x < NEXP) g_count[threadIdx.x] = 0;
}

// ---------------------------------------------------------------------------
// K1: convert x -> fp16
// ---------------------------------------------------------------------------
__global__ void convx_kernel(const float4* __restrict__ x, int n4) {
    int i = blockIdx.x * blockDim.x + threadIdx.x;
    if (i >= n4) return;
    float4 v = x[i];
    __half2 a = __floats2half2_rn(v.x, v.y);
    __half2 b = __floats2half2_rn(v.z, v.w);
    ((uint2*)d_xh)[i] = make_uint2(*(uint32_t*)&a, *(uint32_t*)&b);
}

// ---------------------------------------------------------------------------
// K2: transpose+convert weights: src [e][R][C] fp32 -> dst [e][C][R] fp16
// dst selected in DEVICE code (passing a __device__ symbol from host gives
// the host shadow address -> writes land in host memory via ATS: R3/R4 bug)
// ---------------------------------------------------------------------------
__global__ __launch_bounds__(256)
void trans_kernel(const float* __restrict__ src, int R, int C, int which) {
    __shared__ float t[32][33];
    __half* dstbase = which ? d_w2t : d_w1t;
    int e = blockIdx.z;
    int r0 = blockIdx.x * 32, c0 = blockIdx.y * 32;
    const float* s = src + (size_t)e * R * C;
    __half* d = dstbase + (size_t)e * R * C;
    int tx = threadIdx.x & 31, ty = threadIdx.x >> 5;
#pragma unroll
    for (int p = 0; p < 4; p++)
        t[ty + p * 8][tx] = s[(size_t)(r0 + ty + p * 8) * C + c0 + tx];
    __syncthreads();
#pragma unroll
    for (int p = 0; p < 4; p++)
        d[(size_t)(c0 + ty + p * 8) * R + r0 + tx] =
            __float2half_rn(t[tx][ty + p * 8]);
}

// ---------------------------------------------------------------------------
// K3: router
// ---------------------------------------------------------------------------
__global__ __launch_bounds__(256)
void router_kernel(const float* __restrict__ x,
                   const float* __restrict__ rw,
                   const float* __restrict__ rb) {
    __shared__ float s_rw[DDIM * NEXP];
    __shared__ float s_rb[NEXP];
    for (int i = threadIdx.x; i < DDIM * NEXP; i += 256) s_rw[i] = rw[i];
    if (threadIdx.x < NEXP) s_rb[threadIdx.x] = rb[threadIdx.x];
    __syncthreads();

    int warp = threadIdx.x >> 5, lane = threadIdx.x & 31;
    int t0 = (blockIdx.x * 8 + warp) * 4;
    if (t0 >= T_TOK) return;

    float acc[4][NEXP];
#pragma unroll
    for (int tt = 0; tt < 4; tt++)
#pragma unroll
        for (int e = 0; e < NEXP; e++) acc[tt][e] = 0.f;

#pragma unroll 4
    for (int di = 0; di < 16; di++) {
        int d = di * 32 + lane;
        float xv[4];
#pragma unroll
        for (int tt = 0; tt < 4; tt++) xv[tt] = x[(size_t)(t0 + tt) * DDIM + d];
#pragma unroll
        for (int e = 0; e < NEXP; e++) {
            float w = s_rw[d * NEXP + e];
#pragma unroll
            for (int tt = 0; tt < 4; tt++) acc[tt][e] = fmaf(xv[tt], w, acc[tt][e]);
        }
    }
#pragma unroll
    for (int tt = 0; tt < 4; tt++)
#pragma unroll
        for (int e = 0; e < NEXP; e++) {
            float v = acc[tt][e];
#pragma unroll
            for (int off = 16; off > 0; off >>= 1)
                v += __shfl_xor_sync(0xffffffffu, v, off);
            acc[tt][e] = v;
        }
    if (lane == 0) {
#pragma unroll
        for (int tt = 0; tt < 4; tt++) {
            int t = t0 + tt;
            float v[NEXP];
#pragma unroll
            for (int e = 0; e < NEXP; e++) v[e] = acc[tt][e] + s_rb[e];
            float sv[TOPK]; int si[TOPK];
#pragma unroll
            for (int k = 0; k < TOPK; k++) {
                float bm = -1e30f; int bi = 0;
#pragma unroll
                for (int e = 0; e < NEXP; e++)
                    if (v[e] > bm) { bm = v[e]; bi = e; }
                sv[k] = bm; si[k] = bi; v[bi] = -1e30f;
            }
            float mx = sv[0], s = 0.f, g[TOPK];
#pragma unroll
            for (int k = 0; k < TOPK; k++) { g[k] = __expf(sv[k] - mx); s += g[k]; }
            float inv = 1.f / s;
#pragma unroll
            for (int k = 0; k < TOPK; k++) {
                int e = si[k];
                int pos = atomicAdd(&g_count[e], 1);
                g_tok [e * T_TOK + pos] = t;
                g_gate[e * T_TOK + pos] = g[k] * inv;
            }
        }
    }
}

// ---------------------------------------------------------------------------
// K4: prefix scan of counts
// ---------------------------------------------------------------------------
__global__ void scan_kernel() {
    if (threadIdx.x == 0) {
        int s = 0;
        for (int e = 0; e < NEXP; e++) { g_off[e] = s; s += g_count[e]; }
    }
}

// ---------------------------------------------------------------------------
// K5: GEMM1  H[slot] = relu(gather(X) @ W1^T + b1)   M=128 N=128 K=512
// wmma 16x16x16, 8 warps (4m x 2n), warp tile 32x64, synchronous staging
// ---------------------------------------------------------------------------
__global__ __launch_bounds__(256)
void gemm1_kernel(const float* __restrict__ b1) {
    int e = blockIdx.z;
    int cnt = g_count[e];
    int m0 = blockIdx.y * MTILE;
    if (m0 >= cnt) return;
    int nrows = min(MTILE, cnt - m0);
    int n0 = blockIdx.x * BN;
    int off_e = g_off[e];

    extern __shared__ __align__(16) char dsm[];
    __half* As = (__half*)dsm;                 // 128*72
    __half* Bs = As + MTILE * SA;              // 128*72
    float*  Cs = (float*)dsm;                  // 128*132 (union)
    __shared__ int s_tok[MTILE];

    int tid = threadIdx.x, wid = tid >> 5;
    int wm = wid & 3, wn = wid >> 2;

    if (tid < MTILE) s_tok[tid] = (tid < nrows) ? g_tok[e * T_TOK + m0 + tid] : -1;
    __syncthreads();

    const __half* bsrc = d_w1t + ((size_t)e * HDIM + n0) * DDIM;

    wmma::fragment<wmma::accumulator, 16, 16, 16, float> acc[2][4];
#pragma unroll
    for (int mt = 0; mt < 2; mt++)
#pragma unroll
        for (int nt = 0; nt < 4; nt++) wmma::fill_fragment(acc[mt][nt], 0.f);

    for (int kc = 0; kc < DDIM; kc += BK) {
        __syncthreads();
#pragma unroll
        for (int it = 0; it < 4; it++) {
            int idx = it * 256 + tid;
            int r = idx >> 3, c8 = idx & 7;
            int tok = s_tok[r];
            uint4 v = make_uint4(0, 0, 0, 0);
            if (tok >= 0)
                v = *(const uint4*)(d_xh + (size_t)tok * DDIM + kc + c8 * 8);
            *(uint4*)&As[r * SA + c8 * 8] = v;
        }
#pragma unroll
        for (int it = 0; it < 4; it++) {
            int idx = it * 256 + tid;
            int r = idx >> 3, c8 = idx & 7;
            *(uint4*)&Bs[r * SA + c8 * 8] =
                *(const uint4*)(bsrc + (size_t)r * DDIM + kc + c8 * 8);
        }
        __syncthreads();
#pragma unroll
        for (int ks = 0; ks < BK / 16; ks++) {
            wmma::fragment<wmma::matrix_a, 16, 16, 16, __half, wmma::row_major> af[2];
            wmma::fragment<wmma::matrix_b, 16, 16, 16, __half, wmma::col_major> bf[4];
#pragma unroll
            for (int mt = 0; mt < 2; mt++)
                wmma::load_matrix_sync(af[mt],
                    &As[(wm * 32 + mt * 16) * SA + ks * 16], SA);
#pragma unroll
            for (int nt = 0; nt < 4; nt++)
                wmma::load_matrix_sync(bf[nt],
                    &Bs[(wn * 64 + nt * 16) * SA + ks * 16], SA);
#pragma unroll
            for (int mt = 0; mt < 2; mt++)
#pragma unroll
                for (int nt = 0; nt < 4; nt++)
                    wmma::mma_sync(acc[mt][nt], af[mt], bf[nt], acc[mt][nt]);
        }
    }
    __syncthreads();   // done reading As/Bs before overwriting with Cs
#pragma unroll
    for (int mt = 0; mt < 2; mt++)
#pragma unroll
        for (int nt = 0; nt < 4; nt++)
            wmma::store_matrix_sync(
                &Cs[(wm * 32 + mt * 16) * CLD + wn * 64 + nt * 16],
                acc[mt][nt], CLD, wmma::mem_row_major);
    __syncthreads();

    // epilogue: +b1, relu, fp16 -> hbuf (pairs)
#pragma unroll 4
    for (int i = 0; i < 32; i++) {
        int idx = i * 256 + tid;
        int r = idx >> 6, c2 = (idx & 63) * 2;
        if (r >= nrows) continue;
        float v0 = Cs[r * CLD + c2]     + b1[e * HDIM + n0 + c2];
        float v1 = Cs[r * CLD + c2 + 1] + b1[e * HDIM + n0 + c2 + 1];
        __half2 hh = __floats2half2_rn(fmaxf(v0, 0.f), fmaxf(v1, 0.f));
        *(uint32_t*)&d_hbuf[(size_t)(off_e + m0 + r) * HDIM + n0 + c2] =
            *(uint32_t*)&hh;
    }
}

// ---------------------------------------------------------------------------
// K6: GEMM2  out[tok] += gate * (H @ W2^T + b2)   M=128 N=128 K=2048
// ---------------------------------------------------------------------------
__global__ __launch_bounds__(256)
void gemm2_kernel(const float* __restrict__ b2, float* __restrict__ out) {
    int e = blockIdx.z;
    int cnt = g_count[e];
    int m0 = blockIdx.y * MTILE;
    if (m0 >= cnt) return;
    int nrows = min(MTILE, cnt - m0);
    int n0 = blockIdx.x * BN;
    int off_e = g_off[e];

    extern __shared__ __align__(16) char dsm[];
    __half* As = (__half*)dsm;
    __half* Bs = As + MTILE * SA;
    float*  Cs = (float*)dsm;
    __shared__ int   s_tok[MTILE];
    __shared__ float s_gate[MTILE];

    int tid = threadIdx.x, wid = tid >> 5;
    int wm = wid & 3, wn = wid >> 2;

    if (tid < MTILE) {
        if (tid < nrows) {
            s_tok [tid] = g_tok [e * T_TOK + m0 + tid];
            s_gate[tid] = g_gate[e * T_TOK + m0 + tid];
        } else { s_tok[tid] = 0; s_gate[tid] = 0.f; }
    }
    __syncthreads();

    const __half* asrc = d_hbuf + (size_t)(off_e + m0) * HDIM;
    const __half* bsrc = d_w2t + ((size_t)e * DDIM + n0) * HDIM;

    wmma::fragment<wmma::accumulator, 16, 16, 16, float> acc[2][4];
#pragma unroll
    for (int mt = 0; mt < 2; mt++)
#pragma unroll
        for (int nt = 0; nt < 4; nt++) wmma::fill_fragment(acc[mt][nt], 0.f);

    for (int kc = 0; kc < HDIM; kc += BK) {
        __syncthreads();
#pragma unroll
        for (int it = 0; it < 4; it++) {
            int idx = it * 256 + tid;
            int r = idx >> 3, c8 = idx & 7;
            uint4 v = make_uint4(0, 0, 0, 0);
            if (r < nrows)
                v = *(const uint4*)(asrc + (size_t)r * HDIM + kc + c8 * 8);
            *(uint4*)&As[r * SA + c8 * 8] = v;
        }
#pragma unroll
        for (int it = 0; it < 4; it++) {
            int idx = it * 256 + tid;
            int r = idx >> 3, c8 = idx & 7;
            *(uint4*)&Bs[r * SA + c8 * 8] =
                *(const uint4*)(bsrc + (size_t)r * HDIM + kc + c8 * 8);
        }
        __syncthreads();
#pragma unroll
        for (int ks = 0; ks < BK / 16; ks++) {
            wmma::fragment<wmma::matrix_a, 16, 16, 16, __half, wmma::row_major> af[2];
            wmma::fragment<wmma::matrix_b, 16, 16, 16, __half, wmma::col_major> bf[4];
#pragma unroll
            for (int mt = 0; mt < 2; mt++)
                wmma::load_matrix_sync(af[mt],
                    &As[(wm * 32 + mt * 16) * SA + ks * 16], SA);
#pragma unroll
            for (int nt = 0; nt < 4; nt++)
                wmma::load_matrix_sync(bf[nt],
                    &Bs[(wn * 64 + nt * 16) * SA + ks * 16], SA);
#pragma unroll
            for (int mt = 0; mt < 2; mt++)
#pragma unroll
                for (int nt = 0; nt < 4; nt++)
                    wmma::mma_sync(acc[mt][nt], af[mt], bf[nt], acc[mt][nt]);
        }
    }
    __syncthreads();
#pragma unroll
    for (int mt = 0; mt < 2; mt++)
#pragma unroll
        for (int nt = 0; nt < 4; nt++)
            wmma::store_matrix_sync(
                &Cs[(wm * 32 + mt * 16) * CLD + wn * 64 + nt * 16],
                acc[mt][nt], CLD, wmma::mem_row_major);
    __syncthreads();

    // epilogue: +b2, *gate, atomic scatter
#pragma unroll 4
    for (int i = 0; i < 64; i++) {
        int idx = i * 256 + tid;
        int r = idx >> 7, c = idx & 127;
        if (r >= nrows) continue;
        float v = Cs[r * CLD + c] + b2[e * DDIM + n0 + c];
        atomicAdd(out + (size_t)s_tok[r] * DDIM + n0 + c, s_gate[r] * v);
    }
}

// ---------------------------------------------------------------------------
extern "C" void kernel_launch(void* const* d_in, const int* in_sizes, int n_in,
                              void* d_out, int out_size) {
    const float* x  = (const float*)d_in[0];
    const float* rw = (const float*)d_in[1];
    const float* rb = (const float*)d_in[2];
    const float* w1 = (const float*)d_in[3];
    const float* b1 = (const float*)d_in[4];
    const float* w2 = (const float*)d_in[5];
    const float* b2 = (const float*)d_in[6];
    float* out = (float*)d_out;

    cudaFuncSetAttribute(gemm1_kernel, cudaFuncAttributeMaxDynamicSharedMemorySize, DSM_BYTES);
    cudaFuncSetAttribute(gemm2_kernel, cudaFuncAttributeMaxDynamicSharedMemorySize, DSM_BYTES);

    int n4 = T_TOK * DDIM / 4;
    zero_kernel<<<(n4 + 255) / 256, 256>>>((float4*)out, n4);
    convx_kernel<<<(n4 + 255) / 256, 256>>>((const float4*)x, n4);
    trans_kernel<<<dim3(DDIM / 32, HDIM / 32, NEXP), 256>>>(w1, DDIM, HDIM, 0);
    trans_kernel<<<dim3(HDIM / 32, DDIM / 32, NEXP), 256>>>(w2, HDIM, DDIM, 1);
    router_kernel<<<T_TOK / 32, 256>>>(x, rw, rb);
    scan_kernel<<<1, 32>>>();
    gemm1_kernel<<<dim3(HDIM / BN, T_TOK / MTILE, NEXP), 256, DSM_BYTES>>>(b1);
    gemm2_kernel<<<dim3(DDIM / BN, T_TOK / MTILE, NEXP), 256, DSM_BYTES>>>(b2, out);
}

// round 7
// speedup vs baseline: 28.2693x; 1.2897x over previous
#include <cuda_runtime.h>
#include <cuda_fp16.h>
#include <mma.h>
#include <math.h>
#include <stdint.h>

using namespace nvcuda;

#define T_TOK 16384
#define DDIM  512
#define HDIM  2048
#define NEXP  16
#define TOPK  4

#define MTILE 128
#define BN    128
#define BK    64
#define SA    72            // smem row stride (halves), 144B rows (16B aligned)
#define CLD   132           // epilogue float stage stride
#define SLOTS (T_TOK * TOPK + MTILE)

#define STAGE_HALVES ((MTILE + BN) * SA)                 // one stage: A + B
#define DSM_BYTES    (2 * STAGE_HALVES * 2 > MTILE * CLD * 4 ? \
                      2 * STAGE_HALVES * 2 : MTILE * CLD * 4)   // 73728

// ---------------------------------------------------------------------------
// device scratch (allocation-free)
// ---------------------------------------------------------------------------
__device__ int    g_count[NEXP];
__device__ int    g_off[NEXP];
__device__ int    g_tok [NEXP * T_TOK];
__device__ float  g_gate[NEXP * T_TOK];
__device__ __half d_xh  [(size_t)T_TOK * DDIM];
__device__ __half d_w1t [(size_t)NEXP * HDIM * DDIM];   // [e][n(H)][k(D)]
__device__ __half d_w2t [(size_t)NEXP * DDIM * HDIM];   // [e][n(D)][k(H)]
__device__ __half d_hbuf[(size_t)SLOTS * HDIM];         // fp16 hidden acts

// ---------------------------------------------------------------------------
// helpers
// ---------------------------------------------------------------------------
__device__ __forceinline__ uint32_t smem_u32(const void* p) {
    uint32_t a;
    asm("{ .reg .u64 t; cvta.to.shared.u64 t, %1; cvt.u32.u64 %0, t; }"
        : "=r"(a) : "l"(p));
    return a;
}
#define CP_ASYNC16(dst, src, sz) \
    asm volatile("cp.async.cg.shared.global [%0], [%1], 16, %2;" \
                 :: "r"(dst), "l"(src), "r"(sz) : "memory")
#define CP_COMMIT() asm volatile("cp.async.commit_group;" ::: "memory")
#define CP_WAIT1()  asm volatile("cp.async.wait_group 1;" ::: "memory")
#define CP_WAIT0()  asm volatile("cp.async.wait_group 0;" ::: "memory")

// ---------------------------------------------------------------------------
// K0: zero out + counts
// ---------------------------------------------------------------------------
__global__ void zero_kernel(float4* __restrict__ out, int n4) {
    int i = blockIdx.x * blockDim.x + threadIdx.x;
    if (i < n4) out[i] = make_float4(0.f, 0.f, 0.f, 0.f);
    if (blockIdx.x == 0 && threadIdx.x < NEXP) g_count[threadIdx.x] = 0;
}

// ---------------------------------------------------------------------------
// K1: convert x -> fp16
// ---------------------------------------------------------------------------
__global__ void convx_kernel(const float4* __restrict__ x, int n4) {
    int i = blockIdx.x * blockDim.x + threadIdx.x;
    if (i >= n4) return;
    float4 v = x[i];
    __half2 a = __floats2half2_rn(v.x, v.y);
    __half2 b = __floats2half2_rn(v.z, v.w);
    ((uint2*)d_xh)[i] = make_uint2(*(uint32_t*)&a, *(uint32_t*)&b);
}

// ---------------------------------------------------------------------------
// K2: transpose+convert weights (dst chosen in device code — R4 ATS bug fix)
// ---------------------------------------------------------------------------
__global__ __launch_bounds__(256)
void trans_kernel(const float* __restrict__ src, int R, int C, int which) {
    __shared__ float t[32][33];
    __half* dstbase = which ? d_w2t : d_w1t;
    int e = blockIdx.z;
    int r0 = blockIdx.x * 32, c0 = blockIdx.y * 32;
    const float* s = src + (size_t)e * R * C;
    __half* d = dstbase + (size_t)e * R * C;
    int tx = threadIdx.x & 31, ty = threadIdx.x >> 5;
#pragma unroll
    for (int p = 0; p < 4; p++)
        t[ty + p * 8][tx] = s[(size_t)(r0 + ty + p * 8) * C + c0 + tx];
    __syncthreads();
#pragma unroll
    for (int p = 0; p < 4; p++)
        d[(size_t)(c0 + ty + p * 8) * R + r0 + tx] =
            __float2half_rn(t[tx][ty + p * 8]);
}

// ---------------------------------------------------------------------------
// K3: router
// ---------------------------------------------------------------------------
__global__ __launch_bounds__(256)
void router_kernel(const float* __restrict__ x,
                   const float* __restrict__ rw,
                   const float* __restrict__ rb) {
    __shared__ float s_rw[DDIM * NEXP];
    __shared__ float s_rb[NEXP];
    for (int i = threadIdx.x; i < DDIM * NEXP; i += 256) s_rw[i] = rw[i];
    if (threadIdx.x < NEXP) s_rb[threadIdx.x] = rb[threadIdx.x];
    __syncthreads();

    int warp = threadIdx.x >> 5, lane = threadIdx.x & 31;
    int t0 = (blockIdx.x * 8 + warp) * 4;
    if (t0 >= T_TOK) return;

    float acc[4][NEXP];
#pragma unroll
    for (int tt = 0; tt < 4; tt++)
#pragma unroll
        for (int e = 0; e < NEXP; e++) acc[tt][e] = 0.f;

#pragma unroll 4
    for (int di = 0; di < 16; di++) {
        int d = di * 32 + lane;
        float xv[4];
#pragma unroll
        for (int tt = 0; tt < 4; tt++) xv[tt] = x[(size_t)(t0 + tt) * DDIM + d];
#pragma unroll
        for (int e = 0; e < NEXP; e++) {
            float w = s_rw[d * NEXP + e];
#pragma unroll
            for (int tt = 0; tt < 4; tt++) acc[tt][e] = fmaf(xv[tt], w, acc[tt][e]);
        }
    }
#pragma unroll
    for (int tt = 0; tt < 4; tt++)
#pragma unroll
        for (int e = 0; e < NEXP; e++) {
            float v = acc[tt][e];
#pragma unroll
            for (int off = 16; off > 0; off >>= 1)
                v += __shfl_xor_sync(0xffffffffu, v, off);
            acc[tt][e] = v;
        }
    if (lane == 0) {
#pragma unroll
        for (int tt = 0; tt < 4; tt++) {
            int t = t0 + tt;
            float v[NEXP];
#pragma unroll
            for (int e = 0; e < NEXP; e++) v[e] = acc[tt][e] + s_rb[e];
            float sv[TOPK]; int si[TOPK];
#pragma unroll
            for (int k = 0; k < TOPK; k++) {
                float bm = -1e30f; int bi = 0;
#pragma unroll
                for (int e = 0; e < NEXP; e++)
                    if (v[e] > bm) { bm = v[e]; bi = e; }
                sv[k] = bm; si[k] = bi; v[bi] = -1e30f;
            }
            float mx = sv[0], s = 0.f, g[TOPK];
#pragma unroll
            for (int k = 0; k < TOPK; k++) { g[k] = __expf(sv[k] - mx); s += g[k]; }
            float inv = 1.f / s;
#pragma unroll
            for (int k = 0; k < TOPK; k++) {
                int e = si[k];
                int pos = atomicAdd(&g_count[e], 1);
                g_tok [e * T_TOK + pos] = t;
                g_gate[e * T_TOK + pos] = g[k] * inv;
            }
        }
    }
}

// ---------------------------------------------------------------------------
// K4: prefix scan of counts
// ---------------------------------------------------------------------------
__global__ void scan_kernel() {
    if (threadIdx.x == 0) {
        int s = 0;
        for (int e = 0; e < NEXP; e++) { g_off[e] = s; s += g_count[e]; }
    }
}

// ---------------------------------------------------------------------------
// shared wmma compute on one stage buffer (8 warps, 4m x 2n, warp 32x64)
// ---------------------------------------------------------------------------
__device__ __forceinline__ void wmma_stage(
    const __half* As, const __half* Bs, int wm, int wn,
    wmma::fragment<wmma::accumulator, 16, 16, 16, float> (&acc)[2][4]) {
#pragma unroll
    for (int ks = 0; ks < BK / 16; ks++) {
        wmma::fragment<wmma::matrix_a, 16, 16, 16, __half, wmma::row_major> af[2];
#pragma unroll
        for (int mt = 0; mt < 2; mt++)
            wmma::load_matrix_sync(af[mt],
                &As[(wm * 32 + mt * 16) * SA + ks * 16], SA);
#pragma unroll
        for (int nt = 0; nt < 4; nt++) {
            wmma::fragment<wmma::matrix_b, 16, 16, 16, __half, wmma::col_major> bf;
            wmma::load_matrix_sync(bf,
                &Bs[(wn * 64 + nt * 16) * SA + ks * 16], SA);
            wmma::mma_sync(acc[0][nt], af[0], bf, acc[0][nt]);
            wmma::mma_sync(acc[1][nt], af[1], bf, acc[1][nt]);
        }
    }
}

// ---------------------------------------------------------------------------
// K5: GEMM1  H[slot] = relu(gather(X) @ W1^T + b1)   M=128 N=128 K=512
// cp.async double-buffered pipeline
// ---------------------------------------------------------------------------
__global__ __launch_bounds__(256, 2)
void gemm1_kernel(const float* __restrict__ b1) {
    int e = blockIdx.z;
    int cnt = g_count[e];
    int m0 = blockIdx.y * MTILE;
    if (m0 >= cnt) return;
    int nrows = min(MTILE, cnt - m0);
    int n0 = blockIdx.x * BN;
    int off_e = g_off[e];

    extern __shared__ __align__(16) char dsm[];
    __half* stage[2] = {(__half*)dsm, (__half*)dsm + STAGE_HALVES};
    float*  Cs = (float*)dsm;
    __shared__ int s_tok[MTILE];

    int tid = threadIdx.x, wid = tid >> 5;
    int wm = wid & 3, wn = wid >> 2;

    if (tid < MTILE) s_tok[tid] = (tid < nrows) ? g_tok[e * T_TOK + m0 + tid] : -1;
    __syncthreads();

    const __half* bsrc = d_w1t + ((size_t)e * HDIM + n0) * DDIM;
    const int NC = DDIM / BK;   // 8

#define G1_LOAD(c, buf) do {                                                    \
    int kc = (c) * BK;                                                          \
    __half* As_ = stage[buf];                                                   \
    __half* Bs_ = stage[buf] + MTILE * SA;                                      \
    _Pragma("unroll")                                                           \
    for (int it = 0; it < 4; it++) {                                            \
        int idx = it * 256 + tid;                                               \
        int r = idx >> 3, c8 = idx & 7;                                         \
        int tok = s_tok[r];                                                     \
        const __half* src = d_xh + (size_t)(tok < 0 ? 0 : tok) * DDIM + kc + c8 * 8; \
        CP_ASYNC16(smem_u32(&As_[r * SA + c8 * 8]), src, (tok >= 0) ? 16 : 0);  \
    }                                                                           \
    _Pragma("unroll")                                                           \
    for (int it = 0; it < 4; it++) {                                            \
        int idx = it * 256 + tid;                                               \
        int r = idx >> 3, c8 = idx & 7;                                         \
        CP_ASYNC16(smem_u32(&Bs_[r * SA + c8 * 8]),                             \
                   bsrc + (size_t)r * DDIM + kc + c8 * 8, 16);                  \
    }                                                                           \
    CP_COMMIT();                                                                \
} while (0)

    wmma::fragment<wmma::accumulator, 16, 16, 16, float> acc[2][4];
#pragma unroll
    for (int mt = 0; mt < 2; mt++)
#pragma unroll
        for (int nt = 0; nt < 4; nt++) wmma::fill_fragment(acc[mt][nt], 0.f);

    G1_LOAD(0, 0);
    G1_LOAD(1, 1);

    for (int c = 0; c < NC; c++) {
        if (c + 1 < NC) CP_WAIT1(); else CP_WAIT0();
        __syncthreads();
        int buf = c & 1;
        wmma_stage(stage[buf], stage[buf] + MTILE * SA, wm, wn, acc);
        __syncthreads();
        if (c + 2 < NC) G1_LOAD(c + 2, buf);
    }
#undef G1_LOAD

#pragma unroll
    for (int mt = 0; mt < 2; mt++)
#pragma unroll
        for (int nt = 0; nt < 4; nt++)
            wmma::store_matrix_sync(
                &Cs[(wm * 32 + mt * 16) * CLD + wn * 64 + nt * 16],
                acc[mt][nt], CLD, wmma::mem_row_major);
    __syncthreads();

    // epilogue: +b1, relu, fp16 -> hbuf
#pragma unroll 4
    for (int i = 0; i < 32; i++) {
        int idx = i * 256 + tid;
        int r = idx >> 6, c2 = (idx & 63) * 2;
        if (r >= nrows) continue;
        float v0 = Cs[r * CLD + c2]     + b1[e * HDIM + n0 + c2];
        float v1 = Cs[r * CLD + c2 + 1] + b1[e * HDIM + n0 + c2 + 1];
        __half2 hh = __floats2half2_rn(fmaxf(v0, 0.f), fmaxf(v1, 0.f));
        *(uint32_t*)&d_hbuf[(size_t)(off_e + m0 + r) * HDIM + n0 + c2] =
            *(uint32_t*)&hh;
    }
}

// ---------------------------------------------------------------------------
// K6: GEMM2  out[tok] += gate * (H @ W2^T + b2)   M=128 N=128 K=2048
// ---------------------------------------------------------------------------
__global__ __launch_bounds__(256, 2)
void gemm2_kernel(const float* __restrict__ b2, float* __restrict__ out) {
    int e = blockIdx.z;
    int cnt = g_count[e];
    int m0 = blockIdx.y * MTILE;
    if (m0 >= cnt) return;
    int nrows = min(MTILE, cnt - m0);
    int n0 = blockIdx.x * BN;
    int off_e = g_off[e];

    extern __shared__ __align__(16) char dsm[];
    __half* stage[2] = {(__half*)dsm, (__half*)dsm + STAGE_HALVES};
    float*  Cs = (float*)dsm;
    __shared__ int   s_tok[MTILE];
    __shared__ float s_gate[MTILE];

    int tid = threadIdx.x, wid = tid >> 5;
    int wm = wid & 3, wn = wid >> 2;

    if (tid < MTILE) {
        if (tid < nrows) {
            s_tok [tid] = g_tok [e * T_TOK + m0 + tid];
            s_gate[tid] = g_gate[e * T_TOK + m0 + tid];
        } else { s_tok[tid] = 0; s_gate[tid] = 0.f; }
    }
    __syncthreads();

    const __half* asrc = d_hbuf + (size_t)(off_e + m0) * HDIM;
    const __half* bsrc = d_w2t + ((size_t)e * DDIM + n0) * HDIM;
    const int NC = HDIM / BK;   // 32

#define G2_LOAD(c, buf) do {                                                    \
    int kc = (c) * BK;                                                          \
    __half* As_ = stage[buf];                                                   \
    __half* Bs_ = stage[buf] + MTILE * SA;                                      \
    _Pragma("unroll")                                                           \
    for (int it = 0; it < 4; it++) {                                            \
        int idx = it * 256 + tid;                                               \
        int r = idx >> 3, c8 = idx & 7;                                         \
        int rs = (r < nrows) ? r : 0;                                           \
        CP_ASYNC16(smem_u32(&As_[r * SA + c8 * 8]),                             \
                   asrc + (size_t)rs * HDIM + kc + c8 * 8,                      \
                   (r < nrows) ? 16 : 0);                                       \
    }                                                                           \
    _Pragma("unroll")                                                           \
    for (int it = 0; it < 4; it++) {                                            \
        int idx = it * 256 + tid;                                               \
        int r = idx >> 3, c8 = idx & 7;                                         \
        CP_ASYNC16(smem_u32(&Bs_[r * SA + c8 * 8]),                             \
                   bsrc + (size_t)r * HDIM + kc + c8 * 8, 16);                  \
    }                                                                           \
    CP_COMMIT();                                                                \
} while (0)

    wmma::fragment<wmma::accumulator, 16, 16, 16, float> acc[2][4];
#pragma unroll
    for (int mt = 0; mt < 2; mt++)
#pragma unroll
        for (int nt = 0; nt < 4; nt++) wmma::fill_fragment(acc[mt][nt], 0.f);

    G2_LOAD(0, 0);
    G2_LOAD(1, 1);

    for (int c = 0; c < NC; c++) {
        if (c + 1 < NC) CP_WAIT1(); else CP_WAIT0();
        __syncthreads();
        int buf = c & 1;
        wmma_stage(stage[buf], stage[buf] + MTILE * SA, wm, wn, acc);
        __syncthreads();
        if (c + 2 < NC) G2_LOAD(c + 2, buf);
    }
#undef G2_LOAD

#pragma unroll
    for (int mt = 0; mt < 2; mt++)
#pragma unroll
        for (int nt = 0; nt < 4; nt++)
            wmma::store_matrix_sync(
                &Cs[(wm * 32 + mt * 16) * CLD + wn * 64 + nt * 16],
                acc[mt][nt], CLD, wmma::mem_row_major);
    __syncthreads();

    // epilogue: +b2, *gate, atomic scatter
#pragma unroll 4
    for (int i = 0; i < 64; i++) {
        int idx = i * 256 + tid;
        int r = idx >> 7, c = idx & 127;
        if (r >= nrows) continue;
        float v = Cs[r * CLD + c] + b2[e * DDIM + n0 + c];
        atomicAdd(out + (size_t)s_tok[r] * DDIM + n0 + c, s_gate[r] * v);
    }
}

// ---------------------------------------------------------------------------
extern "C" void kernel_launch(void* const* d_in, const int* in_sizes, int n_in,
                              void* d_out, int out_size) {
    const float* x  = (const float*)d_in[0];
    const float* rw = (const float*)d_in[1];
    const float* rb = (const float*)d_in[2];
    const float* w1 = (const float*)d_in[3];
    const float* b1 = (const float*)d_in[4];
    const float* w2 = (const float*)d_in[5];
    const float* b2 = (const float*)d_in[6];
    float* out = (float*)d_out;

    cudaFuncSetAttribute(gemm1_kernel, cudaFuncAttributeMaxDynamicSharedMemorySize, DSM_BYTES);
    cudaFuncSetAttribute(gemm2_kernel, cudaFuncAttributeMaxDynamicSharedMemorySize, DSM_BYTES);

    int n4 = T_TOK * DDIM / 4;
    zero_kernel<<<(n4 + 255) / 256, 256>>>((float4*)out, n4);
    convx_kernel<<<(n4 + 255) / 256, 256>>>((const float4*)x, n4);
    trans_kernel<<<dim3(DDIM / 32, HDIM / 32, NEXP), 256>>>(w1, DDIM, HDIM, 0);
    trans_kernel<<<dim3(HDIM / 32, DDIM / 32, NEXP), 256>>>(w2, HDIM, DDIM, 1);
    router_kernel<<<T_TOK / 32, 256>>>(x, rw, rb);
    scan_kernel<<<1, 32>>>();
    gemm1_kernel<<<dim3(HDIM / BN, T_TOK / MTILE, NEXP), 256, DSM_BYTES>>>(b1);
    gemm2_kernel<<<dim3(DDIM / BN, T_TOK / MTILE, NEXP), 256, DSM_BYTES>>>(b2, out);
}